// round 13
// baseline (speedup 1.0000x reference)
#include <cuda_runtime.h>
#include <cuda_bf16.h>
#include <cstdint>

// Problem constants
#define B_    8
#define C_    64
#define H_    256
#define W_    256
#define HW_   65536
#define OC_   64
#define P_    16
#define CU_   48
#define OUTC_ 112

// ---------------- device globals -------------------------------------------
__device__ float d_act[B_ * C_];
__device__ int   d_sel[B_ * P_];
__device__ int   d_unsel[B_ * CU_];
// compact per-lane fragment weights: [chunk 9][quad 4][lane 32][4 u32]
// quad q, j4: ni = 2q + (j4>>1); p2 = (j4&1) ? lr+4 : lr   (lq=l>>2, lr=l&3)
__device__ uint32_t d_whi[9 * 4 * 32 * 4];
__device__ uint32_t d_wlo[9 * 4 * 32 * 4];

// ---------------- kernel 0: weight split + fragment quad pack ---------------
__global__ void prep_W_kernel(const float* __restrict__ wgt) {
    for (int i = threadIdx.x; i < 9 * 4 * 32 * 4; i += 256) {
        int chunk = i / 512;
        int rem   = i % 512;
        int q     = rem / 128;
        int rem2  = rem % 128;
        int l     = rem2 / 4;
        int j4    = rem2 % 4;
        int lq = l >> 2, lr = l & 3;
        int ni = 2 * q + (j4 >> 1);
        int p2 = (j4 & 1) ? (lr + 4) : lr;
        int n  = ni * 8 + lq;                          // < 64 always
        float w0 = wgt[n * 144 + (2 * p2) * 9 + chunk];
        float w1 = wgt[n * 144 + (2 * p2 + 1) * 9 + chunk];
        __nv_bfloat16 h0 = __float2bfloat16_rn(w0);
        __nv_bfloat16 h1 = __float2bfloat16_rn(w1);
        __nv_bfloat16 l0 = __float2bfloat16_rn(w0 - __bfloat162float(h0));
        __nv_bfloat16 l1 = __float2bfloat16_rn(w1 - __bfloat162float(h1));
        d_whi[i] = (uint32_t)__bfloat16_as_ushort(h0) | ((uint32_t)__bfloat16_as_ushort(h1) << 16);
        d_wlo[i] = (uint32_t)__bfloat16_as_ushort(l0) | ((uint32_t)__bfloat16_as_ushort(l1) << 16);
    }
}

// ---------------- kernel 1: per-channel min/max + histogram + entropy -------
__global__ void __launch_bounds__(1024, 2)
channel_stats_kernel(const float* __restrict__ x) {
    const int bc  = blockIdx.x;
    const int tid = threadIdx.x;
    const int lane = tid & 31, wid = tid >> 5;
    const float4* xp = reinterpret_cast<const float4*>(x) + (size_t)bc * (HW_ / 4);

    float mn = 3.402823466e38f, mx = -3.402823466e38f;
    for (int i = tid; i < HW_ / 4; i += 1024) {
        float4 v = xp[i];
        mn = fminf(mn, fminf(fminf(v.x, v.y), fminf(v.z, v.w)));
        mx = fmaxf(mx, fmaxf(fmaxf(v.x, v.y), fmaxf(v.z, v.w)));
    }
    #pragma unroll
    for (int off = 16; off > 0; off >>= 1) {
        mn = fminf(mn, __shfl_xor_sync(0xffffffffu, mn, off));
        mx = fmaxf(mx, __shfl_xor_sync(0xffffffffu, mx, off));
    }
    __shared__ float smn[32], smx[32];
    __shared__ float s_mn, s_rng, s_scale;
    if (lane == 0) { smn[wid] = mn; smx[wid] = mx; }
    __syncthreads();
    if (tid == 0) {
        float m = smn[0], M = smx[0];
        #pragma unroll
        for (int i = 1; i < 32; i++) { m = fminf(m, smn[i]); M = fmaxf(M, smx[i]); }
        s_mn = m;
        float rng = __fadd_rn(__fsub_rn(M, m), 1e-8f);
        s_rng = rng;
        s_scale = __fdiv_rn(256.0f, rng);
    }
    __syncthreads();

    __shared__ int h[32][256];
    for (int i = tid; i < 32 * 256; i += 1024) ((int*)h)[i] = 0;
    __syncthreads();
    const float mnv = s_mn, rng = s_rng, sc = s_scale;
    int* hw = h[wid];
    for (int i = tid; i < HW_ / 4; i += 1024) {
        float4 v = xp[i];
        float vals[4] = { v.x, v.y, v.z, v.w };
        #pragma unroll
        for (int k = 0; k < 4; k++) {
            float t = __fsub_rn(vals[k], mnv);
            float a = __fmul_rn(t, sc);
            int bin = (int)a;
            float fr = a - (float)bin;
            float band = __fmaf_rn(4e-7f, a, 1e-6f);
            if (fr < band || fr > 1.0f - band) {
                a = __fmul_rn(__fdiv_rn(t, rng), 256.0f);   // exact path near edges
                bin = (int)a;
            }
            if (bin > 255) bin = 255;
            atomicAdd(&hw[bin], 1);
        }
    }
    __syncthreads();

    __shared__ float hf[256], red[256];
    if (tid < 256) {
        int c = 0;
        #pragma unroll
        for (int w2 = 0; w2 < 32; w2++) c += h[w2][tid];
        hf[tid] = (float)c + 1e-8f;
        red[tid] = hf[tid];
    }
    __syncthreads();
    for (int st = 128; st > 0; st >>= 1) {
        if (tid < st) red[tid] += red[tid + st];
        __syncthreads();
    }
    __shared__ float s_tot;
    if (tid == 0) s_tot = red[0];
    __syncthreads();
    if (tid < 256) {
        float p = hf[tid] / s_tot;
        red[tid] = p * logf(p + 1e-8f);
    }
    __syncthreads();
    for (int st = 128; st > 0; st >>= 1) {
        if (tid < st) red[tid] += red[tid + st];
        __syncthreads();
    }
    if (tid == 0) d_act[bc] = -red[0];
}

// ---------------- kernel 2: top-16 + unselected -----------------------------
__global__ void topk_kernel() {
    int b = threadIdx.x;
    if (b >= B_) return;
    float a[C_];
    bool  m[C_];
    for (int c = 0; c < C_; c++) { a[c] = d_act[b * C_ + c]; m[c] = false; }
    for (int k = 0; k < P_; k++) {
        float best = -3.402823466e38f;
        int bi = 0;
        for (int c = 0; c < C_; c++)
            if (!m[c] && a[c] > best) { best = a[c]; bi = c; }
        d_sel[b * P_ + k] = bi;
        m[bi] = true;
    }
    int j = 0;
    for (int c = 0; c < C_; c++)
        if (!m[c]) d_unsel[b * CU_ + (j++)] = c;
}

// ---------------- kernel 3 (fused): multi-tile mma conv + untouched copy ----
// 512 conv blocks x 4 tiles (2 rows x 128 cols each) with 4-slot row ring.
// Strip: [slot 4][col 132][20 halves], channel pairs (p2, p2+4) interleaved
// so A fragments load as LDS.64. Weights: per-lane quads -> LDS.128.
#define WQ_U32   (9 * 4 * 32 * 4)             // 4608 u32 per blob
#define HPC      20                            // halves per col (16 used)
#define UPC      10                            // u32 per col
#define SLOT_U32 (132 * UPC)                   // 1320
#define STRIP_U32 (4 * SLOT_U32)               // 5280 u32 = 21120 B
#define SM_WHI   0
#define SM_WLO   (WQ_U32 * 4)                  // 18432
#define SM_XHI   (2 * WQ_U32 * 4)              // 36864
#define SM_XLO   (SM_XHI + STRIP_U32 * 4)      // 57984
#define SM_TOTAL (SM_XLO + STRIP_U32 * 4)      // 79104

#define NCONVB 512
#define NCOPY  (B_ * CU_)                      // 384
#define GRID_  (NCONVB + NCOPY)                // 896 = 128 * 7

__device__ __forceinline__ void mma_bf16b(float* d, const uint32_t* a,
                                          uint32_t b0, uint32_t b1) {
    asm volatile(
        "mma.sync.aligned.m16n8k16.row.col.f32.bf16.bf16.f32 "
        "{%0,%1,%2,%3}, {%4,%5,%6,%7}, {%8,%9}, {%0,%1,%2,%3};\n"
        : "+f"(d[0]), "+f"(d[1]), "+f"(d[2]), "+f"(d[3])
        : "r"(a[0]), "r"(a[1]), "r"(a[2]), "r"(a[3]), "r"(b0), "r"(b1));
}

__global__ void __launch_bounds__(256, 2)
conv_copy_kernel(const float* __restrict__ x, const float* __restrict__ bias,
                 float* __restrict__ out) {
    const int tid  = threadIdx.x;
    const int grp  = blockIdx.x / 7;
    const int slot = blockIdx.x % 7;

    // ---------- copy path (3 of every 7 blocks) ----------
    if (slot < 3) {
        int id = grp * 3 + slot;              // 0..383
        int j = id % CU_, b = id / CU_;
        int ch = d_unsel[b * CU_ + j];
        const float4* src = reinterpret_cast<const float4*>(x)
                            + ((size_t)(b * C_ + ch)) * (HW_ / 4);
        float4* dst = reinterpret_cast<float4*>(out)
                      + ((size_t)(b * OUTC_ + OC_ + j)) * (HW_ / 4);
        #pragma unroll 4
        for (int i = tid; i < HW_ / 4; i += 256) dst[i] = src[i];
        return;
    }

    // ---------- conv path ----------
    extern __shared__ char smc[];
    const uint4* ws_hi4 = (const uint4*)(smc + SM_WHI);
    const uint4* ws_lo4 = (const uint4*)(smc + SM_WLO);
    __nv_bfloat16* xs_hi = (__nv_bfloat16*)(smc + SM_XHI);
    __nv_bfloat16* xs_lo = (__nv_bfloat16*)(smc + SM_XLO);
    const uint32_t* xh_u = (const uint32_t*)xs_hi;
    const uint32_t* xl_u = (const uint32_t*)xs_lo;
    __shared__ int ssel[P_];
    __shared__ float sbias[OC_];

    const int q   = grp * 4 + (slot - 3);     // 0..511
    const int b   = q >> 6;
    const int rem = q & 63;
    const int c0  = (rem & 1) * 128;
    const int rgbase = (rem >> 1) * 8;        // 4 row-pairs from here

    if (tid < P_)  ssel[tid]  = d_sel[b * P_ + tid];
    if (tid < OC_) sbias[tid] = bias[tid];
    {   // weight blobs once per block
        uint32_t* wh = (uint32_t*)(smc + SM_WHI);
        uint32_t* wl = (uint32_t*)(smc + SM_WLO);
        for (int i = tid; i < WQ_U32; i += 256) { wh[i] = d_whi[i]; wl[i] = d_wlo[i]; }
    }
    __syncthreads();                           // ssel ready

    const int w  = tid >> 5, l = tid & 31;
    const int warpRow = w >> 2;               // 0 or 1
    const int lq = l >> 2, lr = l & 3;
    const size_t xb_base = ((size_t)(b * C_)) << 16;

    #pragma unroll 1
    for (int ti = 0; ti < 4; ti++) {
        const int r0 = rgbase + ti * 2;

        // ---- stage into ring: 4 rows first tile, 2 rows after ----
        const int nrows = (ti == 0) ? 4 : 2;
        const int gbase = (ti == 0) ? (r0 - 1) : (r0 + 1);
        for (int idx = tid; idx < nrows * 2080; idx += 256) {
            int j   = idx / 2080;              // row within batch
            int r2  = idx % 2080;
            int p   = r2 / 130;                // channel
            int col = r2 % 130;
            int g   = gbase + j;
            int sl  = (g + 4) & 3;
            float v = 0.0f;
            int gc = c0 + col - 1;
            if ((unsigned)g < 256u && (unsigned)gc < 256u)
                v = x[xb_base + ((size_t)ssel[p] << 16) + (g << 8) + gc];
            __nv_bfloat16 hv = __float2bfloat16_rn(v);
            __nv_bfloat16 lv = __float2bfloat16_rn(v - __bfloat162float(hv));
            int p2 = p >> 1;
            int s2 = (((p2 & 3) * 2 + (p2 >> 2)) << 1) + (p & 1);
            int hidx = (sl * 132 + col) * HPC + s2;
            xs_hi[hidx] = hv;
            xs_lo[hidx] = lv;
        }
        __syncthreads();                       // strip ready

        // ring row bases (u32 offsets) for kh = 0..2
        int rbu[3];
        #pragma unroll
        for (int kh = 0; kh < 3; kh++)
            rbu[kh] = (((r0 - 1 + warpRow + kh) + 4) & 3) * SLOT_U32;

        float acc[2][8][4];
        #pragma unroll
        for (int i2 = 0; i2 < 2; i2++)
            #pragma unroll
            for (int ni = 0; ni < 8; ni++)
                #pragma unroll
                for (int r = 0; r < 4; r++) acc[i2][ni][r] = 0.0f;

        #pragma unroll
        for (int chunk = 0; chunk < 9; chunk++) {
            const int kh = chunk / 3, kw = chunk % 3;
            uint4 BH[4];
            #pragma unroll
            for (int qq = 0; qq < 4; qq++)
                BH[qq] = ws_hi4[(chunk * 4 + qq) * 32 + l];

            uint32_t A[2][4];
            #pragma unroll
            for (int mi2 = 0; mi2 < 2; mi2++) {
                const int au = rbu[kh] + ((2 * (w & 3) + mi2) * 16 + lq + kw) * UPC + lr * 2;
                uint2 t0 = *(const uint2*)(xh_u + au);
                uint2 t1 = *(const uint2*)(xh_u + au + 8 * UPC);
                A[mi2][0] = t0.x; A[mi2][1] = t1.x; A[mi2][2] = t0.y; A[mi2][3] = t1.y;
                uint2 s0 = *(const uint2*)(xl_u + au);
                uint2 s1 = *(const uint2*)(xl_u + au + 8 * UPC);
                uint32_t AL[4] = { s0.x, s1.x, s0.y, s1.y };
                #pragma unroll
                for (int qq = 0; qq < 4; qq++) {
                    mma_bf16b(acc[mi2][2 * qq],     A[mi2], BH[qq].x, BH[qq].y);
                    mma_bf16b(acc[mi2][2 * qq + 1], A[mi2], BH[qq].z, BH[qq].w);
                }
                #pragma unroll
                for (int qq = 0; qq < 4; qq++) {
                    mma_bf16b(acc[mi2][2 * qq],     AL, BH[qq].x, BH[qq].y);
                    mma_bf16b(acc[mi2][2 * qq + 1], AL, BH[qq].z, BH[qq].w);
                }
            }
            #pragma unroll
            for (int qq = 0; qq < 4; qq++) {
                uint4 BL = ws_lo4[(chunk * 4 + qq) * 32 + l];
                mma_bf16b(acc[0][2 * qq],     A[0], BL.x, BL.y);
                mma_bf16b(acc[0][2 * qq + 1], A[0], BL.z, BL.w);
                mma_bf16b(acc[1][2 * qq],     A[1], BL.x, BL.y);
                mma_bf16b(acc[1][2 * qq + 1], A[1], BL.z, BL.w);
            }
        }

        // ---- epilogue ----
        const int gr = r0 + warpRow;
        #pragma unroll
        for (int mi2 = 0; mi2 < 2; mi2++) {
            const int pix = (2 * (w & 3) + mi2) * 16 + lq;
            #pragma unroll
            for (int ni = 0; ni < 8; ni++) {
                const int oc0 = ni * 8 + lr * 2;
                float* p0 = out + (((size_t)(b * OUTC_ + oc0)) << 16) + (gr << 8) + c0 + pix;
                float* p1 = p0 + HW_;
                p0[0] = acc[mi2][ni][0] + sbias[oc0];
                p1[0] = acc[mi2][ni][1] + sbias[oc0 + 1];
                p0[8] = acc[mi2][ni][2] + sbias[oc0];
                p1[8] = acc[mi2][ni][3] + sbias[oc0 + 1];
            }
        }
        __syncthreads();                       // protect ring before next stage
    }
}

// ---------------- launch ----------------------------------------------------
extern "C" void kernel_launch(void* const* d_in, const int* in_sizes, int n_in,
                              void* d_out, int out_size) {
    (void)in_sizes; (void)n_in; (void)out_size;
    const float* x    = (const float*)d_in[0];
    const float* wgt  = (const float*)d_in[1];
    const float* bias = (const float*)d_in[2];
    float* out = (float*)d_out;

    cudaFuncSetAttribute(conv_copy_kernel,
                         cudaFuncAttributeMaxDynamicSharedMemorySize, SM_TOTAL);
    cudaFuncSetAttribute(conv_copy_kernel,
                         cudaFuncAttributePreferredSharedMemoryCarveout, 100);

    prep_W_kernel<<<1, 256>>>(wgt);
    channel_stats_kernel<<<B_ * C_, 1024>>>(x);
    topk_kernel<<<1, 8>>>();
    conv_copy_kernel<<<GRID_, 256, SM_TOTAL>>>(x, bias, out);
}

// round 14
// speedup vs baseline: 1.0007x; 1.0007x over previous
#include <cuda_runtime.h>
#include <cuda_bf16.h>
#include <cstdint>

// Problem constants
#define B_    8
#define C_    64
#define H_    256
#define W_    256
#define HW_   65536
#define OC_   64
#define P_    16
#define CU_   48
#define OUTC_ 112

// ---------------- device globals -------------------------------------------
__device__ float d_act[B_ * C_];
__device__ int   d_sel[B_ * P_];
__device__ int   d_unsel[B_ * CU_];
// compact per-lane fragment weights: [chunk 9][quad 4][lane 32][4 u32]
__device__ uint32_t d_whi[9 * 4 * 32 * 4];
__device__ uint32_t d_wlo[9 * 4 * 32 * 4];

// ---------------- PTX helpers ----------------------------------------------
__device__ __forceinline__ uint32_t smem_u32(const void* p) {
    uint32_t a;
    asm("{ .reg .u64 t; cvta.to.shared.u64 t, %1; cvt.u32.u64 %0, t; }" : "=r"(a) : "l"(p));
    return a;
}
__device__ __forceinline__ void cp_async4(uint32_t saddr, const void* gptr, int src_bytes) {
    asm volatile("cp.async.ca.shared.global [%0], [%1], 4, %2;"
                 :: "r"(saddr), "l"(gptr), "r"(src_bytes) : "memory");
}
#define CP_COMMIT() asm volatile("cp.async.commit_group;" ::: "memory")
#define CP_WAIT(n)  asm volatile("cp.async.wait_group %0;" :: "n"(n) : "memory")

// ---------------- kernel 0: weight split + fragment quad pack ---------------
__global__ void prep_W_kernel(const float* __restrict__ wgt) {
    for (int i = threadIdx.x; i < 9 * 4 * 32 * 4; i += 256) {
        int chunk = i / 512;
        int rem   = i % 512;
        int q     = rem / 128;
        int rem2  = rem % 128;
        int l     = rem2 / 4;
        int j4    = rem2 % 4;
        int lq = l >> 2, lr = l & 3;
        int ni = 2 * q + (j4 >> 1);
        int p2 = (j4 & 1) ? (lr + 4) : lr;
        int n  = ni * 8 + lq;
        float w0 = wgt[n * 144 + (2 * p2) * 9 + chunk];
        float w1 = wgt[n * 144 + (2 * p2 + 1) * 9 + chunk];
        __nv_bfloat16 h0 = __float2bfloat16_rn(w0);
        __nv_bfloat16 h1 = __float2bfloat16_rn(w1);
        __nv_bfloat16 l0 = __float2bfloat16_rn(w0 - __bfloat162float(h0));
        __nv_bfloat16 l1 = __float2bfloat16_rn(w1 - __bfloat162float(h1));
        d_whi[i] = (uint32_t)__bfloat16_as_ushort(h0) | ((uint32_t)__bfloat16_as_ushort(h1) << 16);
        d_wlo[i] = (uint32_t)__bfloat16_as_ushort(l0) | ((uint32_t)__bfloat16_as_ushort(l1) << 16);
    }
}

// ---------------- kernel 1: per-channel min/max + histogram + entropy -------
__global__ void __launch_bounds__(1024, 2)
channel_stats_kernel(const float* __restrict__ x) {
    const int bc  = blockIdx.x;
    const int tid = threadIdx.x;
    const int lane = tid & 31, wid = tid >> 5;
    const float4* xp = reinterpret_cast<const float4*>(x) + (size_t)bc * (HW_ / 4);

    float mn = 3.402823466e38f, mx = -3.402823466e38f;
    for (int i = tid; i < HW_ / 4; i += 1024) {
        float4 v = xp[i];
        mn = fminf(mn, fminf(fminf(v.x, v.y), fminf(v.z, v.w)));
        mx = fmaxf(mx, fmaxf(fmaxf(v.x, v.y), fmaxf(v.z, v.w)));
    }
    #pragma unroll
    for (int off = 16; off > 0; off >>= 1) {
        mn = fminf(mn, __shfl_xor_sync(0xffffffffu, mn, off));
        mx = fmaxf(mx, __shfl_xor_sync(0xffffffffu, mx, off));
    }
    __shared__ float smn[32], smx[32];
    __shared__ float s_mn, s_rng, s_scale;
    if (lane == 0) { smn[wid] = mn; smx[wid] = mx; }
    __syncthreads();
    if (tid == 0) {
        float m = smn[0], M = smx[0];
        #pragma unroll
        for (int i = 1; i < 32; i++) { m = fminf(m, smn[i]); M = fmaxf(M, smx[i]); }
        s_mn = m;
        float rng = __fadd_rn(__fsub_rn(M, m), 1e-8f);
        s_rng = rng;
        s_scale = __fdiv_rn(256.0f, rng);
    }
    __syncthreads();

    __shared__ int h[32][256];
    for (int i = tid; i < 32 * 256; i += 1024) ((int*)h)[i] = 0;
    __syncthreads();
    const float mnv = s_mn, rng = s_rng, sc = s_scale;
    int* hw = h[wid];
    for (int i = tid; i < HW_ / 4; i += 1024) {
        float4 v = xp[i];
        float vals[4] = { v.x, v.y, v.z, v.w };
        #pragma unroll
        for (int k = 0; k < 4; k++) {
            float t = __fsub_rn(vals[k], mnv);
            float a = __fmul_rn(t, sc);
            int bin = (int)a;
            float fr = a - (float)bin;
            float band = __fmaf_rn(4e-7f, a, 1e-6f);
            if (fr < band || fr > 1.0f - band) {
                a = __fmul_rn(__fdiv_rn(t, rng), 256.0f);   // exact path near edges
                bin = (int)a;
            }
            if (bin > 255) bin = 255;
            atomicAdd(&hw[bin], 1);
        }
    }
    __syncthreads();

    __shared__ float hf[256], red[256];
    if (tid < 256) {
        int c = 0;
        #pragma unroll
        for (int w2 = 0; w2 < 32; w2++) c += h[w2][tid];
        hf[tid] = (float)c + 1e-8f;
        red[tid] = hf[tid];
    }
    __syncthreads();
    for (int st = 128; st > 0; st >>= 1) {
        if (tid < st) red[tid] += red[tid + st];
        __syncthreads();
    }
    __shared__ float s_tot;
    if (tid == 0) s_tot = red[0];
    __syncthreads();
    if (tid < 256) {
        float p = hf[tid] / s_tot;
        red[tid] = p * logf(p + 1e-8f);
    }
    __syncthreads();
    for (int st = 128; st > 0; st >>= 1) {
        if (tid < st) red[tid] += red[tid + st];
        __syncthreads();
    }
    if (tid == 0) d_act[bc] = -red[0];
}

// ---------------- kernel 2: top-16 + unselected -----------------------------
__global__ void topk_kernel() {
    int b = threadIdx.x;
    if (b >= B_) return;
    float a[C_];
    bool  m[C_];
    for (int c = 0; c < C_; c++) { a[c] = d_act[b * C_ + c]; m[c] = false; }
    for (int k = 0; k < P_; k++) {
        float best = -3.402823466e38f;
        int bi = 0;
        for (int c = 0; c < C_; c++)
            if (!m[c] && a[c] > best) { best = a[c]; bi = c; }
        d_sel[b * P_ + k] = bi;
        m[bi] = true;
    }
    int j = 0;
    for (int c = 0; c < C_; c++)
        if (!m[c]) d_unsel[b * CU_ + (j++)] = c;
}

// ---------------- kernel 3 (fused): cp.async-pipelined mma conv + copy ------
// 512 conv blocks x 4 tiles (2 rows x 128 cols) with 4-slot bf16 row ring.
// Raw fp32 rows for tile t+1 arrive via cp.async while tile t computes;
// a smem->smem convert pass splits to bf16 hi/lo ring slots.
#define WQ_U32   (9 * 4 * 32 * 4)             // 4608 u32 per blob
#define HPC      20                            // halves per col (16 used)
#define UPC      10                            // u32 per col
#define SLOT_U32 (132 * UPC)                   // 1320
#define STRIP_U32 (4 * SLOT_U32)               // 5280 u32
#define RAW_U32  (2 * 16 * 130)                // 4160 fp32 per buffer
#define SM_WHI   0
#define SM_WLO   (WQ_U32 * 4)                  // 18432
#define SM_XHI   (2 * WQ_U32 * 4)              // 36864
#define SM_XLO   (SM_XHI + STRIP_U32 * 4)      // 57984
#define SM_RAW   (SM_XLO + STRIP_U32 * 4)      // 79104
#define SM_TOTAL (SM_RAW + 2 * RAW_U32 * 4)    // 112384

#define NCONVB 512
#define NCOPY  (B_ * CU_)                      // 384
#define GRID_  (NCONVB + NCOPY)                // 896 = 128 * 7

__device__ __forceinline__ void mma_bf16b(float* d, const uint32_t* a,
                                          uint32_t b0, uint32_t b1) {
    asm volatile(
        "mma.sync.aligned.m16n8k16.row.col.f32.bf16.bf16.f32 "
        "{%0,%1,%2,%3}, {%4,%5,%6,%7}, {%8,%9}, {%0,%1,%2,%3};\n"
        : "+f"(d[0]), "+f"(d[1]), "+f"(d[2]), "+f"(d[3])
        : "r"(a[0]), "r"(a[1]), "r"(a[2]), "r"(a[3]), "r"(b0), "r"(b1));
}

__global__ void __launch_bounds__(256, 2)
conv_copy_kernel(const float* __restrict__ x, const float* __restrict__ bias,
                 float* __restrict__ out) {
    const int tid  = threadIdx.x;
    const int grp  = blockIdx.x / 7;
    const int slot = blockIdx.x % 7;

    // ---------- copy path (3 of every 7 blocks) ----------
    if (slot < 3) {
        int id = grp * 3 + slot;
        int j = id % CU_, b = id / CU_;
        int ch = d_unsel[b * CU_ + j];
        const float4* src = reinterpret_cast<const float4*>(x)
                            + ((size_t)(b * C_ + ch)) * (HW_ / 4);
        float4* dst = reinterpret_cast<float4*>(out)
                      + ((size_t)(b * OUTC_ + OC_ + j)) * (HW_ / 4);
        #pragma unroll 4
        for (int i = tid; i < HW_ / 4; i += 256) dst[i] = src[i];
        return;
    }

    // ---------- conv path ----------
    extern __shared__ char smc[];
    const uint4* ws_hi4 = (const uint4*)(smc + SM_WHI);
    const uint4* ws_lo4 = (const uint4*)(smc + SM_WLO);
    __nv_bfloat16* xs_hi = (__nv_bfloat16*)(smc + SM_XHI);
    __nv_bfloat16* xs_lo = (__nv_bfloat16*)(smc + SM_XLO);
    float* rawf = (float*)(smc + SM_RAW);
    const uint32_t* xh_u = (const uint32_t*)xs_hi;
    const uint32_t* xl_u = (const uint32_t*)xs_lo;
    const uint32_t raw_base = smem_u32(rawf);
    __shared__ int ssel[P_];
    __shared__ float sbias[OC_];

    const int q   = grp * 4 + (slot - 3);     // 0..511
    const int b   = q >> 6;
    const int rem = q & 63;
    const int c0  = (rem & 1) * 128;
    const int rgbase = (rem >> 1) * 8;        // 4 row-pairs from here

    if (tid < P_)  ssel[tid]  = d_sel[b * P_ + tid];
    if (tid < OC_) sbias[tid] = bias[tid];
    {
        uint32_t* wh = (uint32_t*)(smc + SM_WHI);
        uint32_t* wl = (uint32_t*)(smc + SM_WLO);
        for (int i = tid; i < WQ_U32; i += 256) { wh[i] = d_whi[i]; wl[i] = d_wlo[i]; }
    }
    __syncthreads();                           // ssel ready

    const int w  = tid >> 5, l = tid & 31;
    const int warpRow = w >> 2;
    const int lq = l >> 2, lr = l & 3;
    const size_t xb_base = ((size_t)(b * C_)) << 16;

    // ---- prologue: direct-stage rows rgbase-1 .. rgbase+2 ----
    for (int idx = tid; idx < 4 * 2080; idx += 256) {
        int j   = idx / 2080;
        int r2  = idx % 2080;
        int p   = r2 / 130;
        int col = r2 % 130;
        int g   = rgbase - 1 + j;
        int sl  = (g + 4) & 3;
        float v = 0.0f;
        int gc = c0 + col - 1;
        if ((unsigned)g < 256u && (unsigned)gc < 256u)
            v = x[xb_base + ((size_t)ssel[p] << 16) + (g << 8) + gc];
        __nv_bfloat16 hv = __float2bfloat16_rn(v);
        __nv_bfloat16 lv = __float2bfloat16_rn(v - __bfloat162float(hv));
        int p2 = p >> 1;
        int s2 = (((p2 & 3) * 2 + (p2 >> 2)) << 1) + (p & 1);
        int hidx = (sl * 132 + col) * HPC + s2;
        xs_hi[hidx] = hv;
        xs_lo[hidx] = lv;
    }
    // ---- prologue prefetch: rows rgbase+3, rgbase+4 -> raw buf 0 ----
    for (int idx = tid; idx < RAW_U32; idx += 256) {
        int j   = idx / 2080;
        int r2  = idx % 2080;
        int p   = r2 / 130;
        int col = r2 % 130;
        int g   = rgbase + 3 + j;
        int gc  = c0 + col - 1;
        int ok  = ((unsigned)g < 256u && (unsigned)gc < 256u) ? 4 : 0;
        const float* gp = x + xb_base + ((size_t)ssel[p] << 16)
                        + ((g & 255) << 8) + (ok ? gc : 0);
        cp_async4(raw_base + (uint32_t)idx * 4u, gp, ok);
    }
    CP_COMMIT();

    #pragma unroll 1
    for (int ti = 0; ti < 4; ti++) {
        const int r0 = rgbase + ti * 2;
        __syncthreads();                       // ring consistent

        int rbu[3];
        #pragma unroll
        for (int kh = 0; kh < 3; kh++)
            rbu[kh] = (((r0 - 1 + warpRow + kh) + 4) & 3) * SLOT_U32;

        float acc[2][8][4];
        #pragma unroll
        for (int i2 = 0; i2 < 2; i2++)
            #pragma unroll
            for (int ni = 0; ni < 8; ni++)
                #pragma unroll
                for (int r = 0; r < 4; r++) acc[i2][ni][r] = 0.0f;

        #pragma unroll
        for (int chunk = 0; chunk < 9; chunk++) {
            const int kh = chunk / 3, kw = chunk % 3;
            uint4 BH[4];
            #pragma unroll
            for (int qq = 0; qq < 4; qq++)
                BH[qq] = ws_hi4[(chunk * 4 + qq) * 32 + l];

            uint32_t A[2][4];
            #pragma unroll
            for (int mi2 = 0; mi2 < 2; mi2++) {
                const int au = rbu[kh] + ((2 * (w & 3) + mi2) * 16 + lq + kw) * UPC + lr * 2;
                uint2 t0 = *(const uint2*)(xh_u + au);
                uint2 t1 = *(const uint2*)(xh_u + au + 8 * UPC);
                A[mi2][0] = t0.x; A[mi2][1] = t1.x; A[mi2][2] = t0.y; A[mi2][3] = t1.y;
                uint2 s0 = *(const uint2*)(xl_u + au);
                uint2 s1 = *(const uint2*)(xl_u + au + 8 * UPC);
                uint32_t AL[4] = { s0.x, s1.x, s0.y, s1.y };
                #pragma unroll
                for (int qq = 0; qq < 4; qq++) {
                    mma_bf16b(acc[mi2][2 * qq],     A[mi2], BH[qq].x, BH[qq].y);
                    mma_bf16b(acc[mi2][2 * qq + 1], A[mi2], BH[qq].z, BH[qq].w);
                }
                #pragma unroll
                for (int qq = 0; qq < 4; qq++) {
                    mma_bf16b(acc[mi2][2 * qq],     AL, BH[qq].x, BH[qq].y);
                    mma_bf16b(acc[mi2][2 * qq + 1], AL, BH[qq].z, BH[qq].w);
                }
            }
            #pragma unroll
            for (int qq = 0; qq < 4; qq++) {
                uint4 BL = ws_lo4[(chunk * 4 + qq) * 32 + l];
                mma_bf16b(acc[0][2 * qq],     A[0], BL.x, BL.y);
                mma_bf16b(acc[0][2 * qq + 1], A[0], BL.z, BL.w);
                mma_bf16b(acc[1][2 * qq],     A[1], BL.x, BL.y);
                mma_bf16b(acc[1][2 * qq + 1], A[1], BL.z, BL.w);
            }
        }

        // ---- epilogue ----
        const int gr = r0 + warpRow;
        #pragma unroll
        for (int mi2 = 0; mi2 < 2; mi2++) {
            const int pix = (2 * (w & 3) + mi2) * 16 + lq;
            #pragma unroll
            for (int ni = 0; ni < 8; ni++) {
                const int oc0 = ni * 8 + lr * 2;
                float* p0 = out + (((size_t)(b * OUTC_ + oc0)) << 16) + (gr << 8) + c0 + pix;
                float* p1 = p0 + HW_;
                p0[0] = acc[mi2][ni][0] + sbias[oc0];
                p1[0] = acc[mi2][ni][1] + sbias[oc0 + 1];
                p0[8] = acc[mi2][ni][2] + sbias[oc0];
                p1[8] = acc[mi2][ni][3] + sbias[oc0 + 1];
            }
        }
        __syncthreads();                       // everyone done reading ring

        if (ti < 3) {
            // issue prefetch for tile ti+2 (rows r0+5, r0+6) into other buffer
            if (ti < 2) {
                const uint32_t rb2 = raw_base + (uint32_t)(((ti + 1) & 1) * RAW_U32) * 4u;
                for (int idx = tid; idx < RAW_U32; idx += 256) {
                    int j   = idx / 2080;
                    int r2  = idx % 2080;
                    int p   = r2 / 130;
                    int col = r2 % 130;
                    int g   = r0 + 5 + j;
                    int gc  = c0 + col - 1;
                    int ok  = ((unsigned)g < 256u && (unsigned)gc < 256u) ? 4 : 0;
                    const float* gp = x + xb_base + ((size_t)ssel[p] << 16)
                                    + ((g & 255) << 8) + (ok ? gc : 0);
                    cp_async4(rb2 + (uint32_t)idx * 4u, gp, ok);
                }
                CP_COMMIT();
                CP_WAIT(1);                    // rows for tile ti+1 landed
            } else {
                CP_WAIT(0);
            }
            // convert raw buf[ti&1] (rows r0+3, r0+4) into ring slots
            const float* rbf = rawf + (ti & 1) * RAW_U32;
            for (int idx = tid; idx < RAW_U32; idx += 256) {
                int j   = idx / 2080;
                int r2  = idx % 2080;
                int p   = r2 / 130;
                int col = r2 % 130;
                int g   = r0 + 3 + j;
                int sl  = (g + 4) & 3;
                float v = rbf[idx];
                __nv_bfloat16 hv = __float2bfloat16_rn(v);
                __nv_bfloat16 lv = __float2bfloat16_rn(v - __bfloat162float(hv));
                int p2 = p >> 1;
                int s2 = (((p2 & 3) * 2 + (p2 >> 2)) << 1) + (p & 1);
                int hidx = (sl * 132 + col) * HPC + s2;
                xs_hi[hidx] = hv;
                xs_lo[hidx] = lv;
            }
        }
    }
}

// ---------------- launch ----------------------------------------------------
extern "C" void kernel_launch(void* const* d_in, const int* in_sizes, int n_in,
                              void* d_out, int out_size) {
    (void)in_sizes; (void)n_in; (void)out_size;
    const float* x    = (const float*)d_in[0];
    const float* wgt  = (const float*)d_in[1];
    const float* bias = (const float*)d_in[2];
    float* out = (float*)d_out;

    cudaFuncSetAttribute(conv_copy_kernel,
                         cudaFuncAttributeMaxDynamicSharedMemorySize, SM_TOTAL);
    cudaFuncSetAttribute(conv_copy_kernel,
                         cudaFuncAttributePreferredSharedMemoryCarveout, 100);

    prep_W_kernel<<<1, 256>>>(wgt);
    channel_stats_kernel<<<B_ * C_, 1024>>>(x);
    topk_kernel<<<1, 8>>>();
    conv_copy_kernel<<<GRID_, 256, SM_TOTAL>>>(x, bias, out);
}

// round 15
// speedup vs baseline: 1.0273x; 1.0266x over previous
#include <cuda_runtime.h>
#include <cuda_bf16.h>
#include <cstdint>

// Problem constants
#define B_    8
#define C_    64
#define H_    256
#define W_    256
#define HW_   65536
#define OC_   64
#define P_    16
#define CU_   48
#define OUTC_ 112

// ---------------- device globals -------------------------------------------
__device__ float d_act[B_ * C_];
__device__ int   d_sel[B_ * P_];
__device__ int   d_unsel[B_ * CU_];
// compact per-lane fragment weights: [chunk 9][quad 4][lane 32][4 u32]
__device__ uint32_t d_whi[9 * 4 * 32 * 4];
__device__ uint32_t d_wlo[9 * 4 * 32 * 4];

// ---------------- kernel 0: weight split + fragment quad pack ---------------
__global__ void prep_W_kernel(const float* __restrict__ wgt) {
    for (int i = threadIdx.x; i < 9 * 4 * 32 * 4; i += 256) {
        int chunk = i / 512;
        int rem   = i % 512;
        int q     = rem / 128;
        int rem2  = rem % 128;
        int l     = rem2 / 4;
        int j4    = rem2 % 4;
        int lq = l >> 2, lr = l & 3;
        int ni = 2 * q + (j4 >> 1);
        int p2 = (j4 & 1) ? (lr + 4) : lr;
        int n  = ni * 8 + lq;
        float w0 = wgt[n * 144 + (2 * p2) * 9 + chunk];
        float w1 = wgt[n * 144 + (2 * p2 + 1) * 9 + chunk];
        __nv_bfloat16 h0 = __float2bfloat16_rn(w0);
        __nv_bfloat16 h1 = __float2bfloat16_rn(w1);
        __nv_bfloat16 l0 = __float2bfloat16_rn(w0 - __bfloat162float(h0));
        __nv_bfloat16 l1 = __float2bfloat16_rn(w1 - __bfloat162float(h1));
        d_whi[i] = (uint32_t)__bfloat16_as_ushort(h0) | ((uint32_t)__bfloat16_as_ushort(h1) << 16);
        d_wlo[i] = (uint32_t)__bfloat16_as_ushort(l0) | ((uint32_t)__bfloat16_as_ushort(l1) << 16);
    }
}

// ---------------- kernel 1: per-channel min/max + histogram + entropy -------
__global__ void __launch_bounds__(1024, 2)
channel_stats_kernel(const float* __restrict__ x) {
    const int bc  = blockIdx.x;
    const int tid = threadIdx.x;
    const int lane = tid & 31, wid = tid >> 5;
    const float4* xp = reinterpret_cast<const float4*>(x) + (size_t)bc * (HW_ / 4);

    float mn = 3.402823466e38f, mx = -3.402823466e38f;
    for (int i = tid; i < HW_ / 4; i += 1024) {
        float4 v = xp[i];
        mn = fminf(mn, fminf(fminf(v.x, v.y), fminf(v.z, v.w)));
        mx = fmaxf(mx, fmaxf(fmaxf(v.x, v.y), fmaxf(v.z, v.w)));
    }
    #pragma unroll
    for (int off = 16; off > 0; off >>= 1) {
        mn = fminf(mn, __shfl_xor_sync(0xffffffffu, mn, off));
        mx = fmaxf(mx, __shfl_xor_sync(0xffffffffu, mx, off));
    }
    __shared__ float smn[32], smx[32];
    __shared__ float s_mn, s_rng, s_scale;
    if (lane == 0) { smn[wid] = mn; smx[wid] = mx; }
    __syncthreads();
    if (tid == 0) {
        float m = smn[0], M = smx[0];
        #pragma unroll
        for (int i = 1; i < 32; i++) { m = fminf(m, smn[i]); M = fmaxf(M, smx[i]); }
        s_mn = m;
        float rng = __fadd_rn(__fsub_rn(M, m), 1e-8f);
        s_rng = rng;
        s_scale = __fdiv_rn(256.0f, rng);
    }
    __syncthreads();

    __shared__ int h[32][256];
    for (int i = tid; i < 32 * 256; i += 1024) ((int*)h)[i] = 0;
    __syncthreads();
    const float mnv = s_mn, rng = s_rng, sc = s_scale;
    int* hw = h[wid];
    for (int i = tid; i < HW_ / 4; i += 1024) {
        float4 v = xp[i];
        float vals[4] = { v.x, v.y, v.z, v.w };
        #pragma unroll
        for (int k = 0; k < 4; k++) {
            float t = __fsub_rn(vals[k], mnv);
            float a = __fmul_rn(t, sc);
            int bin = (int)a;
            float fr = a - (float)bin;
            float band = __fmaf_rn(4e-7f, a, 1e-6f);
            if (fr < band || fr > 1.0f - band) {
                a = __fmul_rn(__fdiv_rn(t, rng), 256.0f);   // exact path near edges
                bin = (int)a;
            }
            if (bin > 255) bin = 255;
            atomicAdd(&hw[bin], 1);
        }
    }
    __syncthreads();

    __shared__ float hf[256], red[256];
    if (tid < 256) {
        int c = 0;
        #pragma unroll
        for (int w2 = 0; w2 < 32; w2++) c += h[w2][tid];
        hf[tid] = (float)c + 1e-8f;
        red[tid] = hf[tid];
    }
    __syncthreads();
    for (int st = 128; st > 0; st >>= 1) {
        if (tid < st) red[tid] += red[tid + st];
        __syncthreads();
    }
    __shared__ float s_tot;
    if (tid == 0) s_tot = red[0];
    __syncthreads();
    if (tid < 256) {
        float p = hf[tid] / s_tot;
        red[tid] = p * logf(p + 1e-8f);
    }
    __syncthreads();
    for (int st = 128; st > 0; st >>= 1) {
        if (tid < st) red[tid] += red[tid + st];
        __syncthreads();
    }
    if (tid == 0) d_act[bc] = -red[0];
}

// ---------------- kernel 2: top-16 + unselected -----------------------------
__global__ void topk_kernel() {
    int b = threadIdx.x;
    if (b >= B_) return;
    float a[C_];
    bool  m[C_];
    for (int c = 0; c < C_; c++) { a[c] = d_act[b * C_ + c]; m[c] = false; }
    for (int k = 0; k < P_; k++) {
        float best = -3.402823466e38f;
        int bi = 0;
        for (int c = 0; c < C_; c++)
            if (!m[c] && a[c] > best) { best = a[c]; bi = c; }
        d_sel[b * P_ + k] = bi;
        m[bi] = true;
    }
    int j = 0;
    for (int c = 0; c < C_; c++)
        if (!m[c]) d_unsel[b * CU_ + (j++)] = c;
}

// ---------------- kernel 3 (fused): 3-CTA/SM mma conv + untouched copy ------
// 512 conv blocks x 8 tiles (1 row x 128 cols each), 3-slot bf16 row ring.
// Warp = 16 pixels x all 64 ocs; acc[8][4] = 32 regs -> 3 CTAs/SM.
#define WQ_U32   (9 * 4 * 32 * 4)             // 4608 u32 per blob
#define HPC      20                            // halves per col (16 used)
#define UPC      10                            // u32 per col
#define SLOT_U32 (132 * UPC)                   // 1320
#define STRIP_U32 (3 * SLOT_U32)               // 3960 u32 (3-slot ring)
#define SM_WHI   0
#define SM_WLO   (WQ_U32 * 4)                  // 18432
#define SM_XHI   (2 * WQ_U32 * 4)              // 36864
#define SM_XLO   (SM_XHI + STRIP_U32 * 4)      // 52704
#define SM_TOTAL (SM_XLO + STRIP_U32 * 4)      // 68544 bytes (<= 76KB for 3 CTAs)

#define NCONVB 512
#define NCOPY  (B_ * CU_)                      // 384
#define GRID_  (NCONVB + NCOPY)                // 896 = 128 * 7

__device__ __forceinline__ void mma_bf16b(float* d, const uint32_t* a,
                                          uint32_t b0, uint32_t b1) {
    asm volatile(
        "mma.sync.aligned.m16n8k16.row.col.f32.bf16.bf16.f32 "
        "{%0,%1,%2,%3}, {%4,%5,%6,%7}, {%8,%9}, {%0,%1,%2,%3};\n"
        : "+f"(d[0]), "+f"(d[1]), "+f"(d[2]), "+f"(d[3])
        : "r"(a[0]), "r"(a[1]), "r"(a[2]), "r"(a[3]), "r"(b0), "r"(b1));
}

__global__ void __launch_bounds__(256, 3)
conv_copy_kernel(const float* __restrict__ x, const float* __restrict__ bias,
                 float* __restrict__ out) {
    const int tid  = threadIdx.x;
    const int grp  = blockIdx.x / 7;
    const int slot = blockIdx.x % 7;

    // ---------- copy path (3 of every 7 blocks) ----------
    if (slot < 3) {
        int id = grp * 3 + slot;
        int j = id % CU_, b = id / CU_;
        int ch = d_unsel[b * CU_ + j];
        const float4* src = reinterpret_cast<const float4*>(x)
                            + ((size_t)(b * C_ + ch)) * (HW_ / 4);
        float4* dst = reinterpret_cast<float4*>(out)
                      + ((size_t)(b * OUTC_ + OC_ + j)) * (HW_ / 4);
        #pragma unroll 4
        for (int i = tid; i < HW_ / 4; i += 256) dst[i] = src[i];
        return;
    }

    // ---------- conv path ----------
    extern __shared__ char smc[];
    const uint4* ws_hi4 = (const uint4*)(smc + SM_WHI);
    const uint4* ws_lo4 = (const uint4*)(smc + SM_WLO);
    __nv_bfloat16* xs_hi = (__nv_bfloat16*)(smc + SM_XHI);
    __nv_bfloat16* xs_lo = (__nv_bfloat16*)(smc + SM_XLO);
    const uint32_t* xh_u = (const uint32_t*)xs_hi;
    const uint32_t* xl_u = (const uint32_t*)xs_lo;
    __shared__ int ssel[P_];
    __shared__ float sbias[OC_];

    const int q   = grp * 4 + (slot - 3);     // 0..511
    const int b   = q >> 6;
    const int rem = q & 63;
    const int c0  = (rem & 1) * 128;
    const int rgbase = (rem >> 1) * 8;        // 8 consecutive rows

    if (tid < P_)  ssel[tid]  = d_sel[b * P_ + tid];
    if (tid < OC_) sbias[tid] = bias[tid];
    {
        uint32_t* wh = (uint32_t*)(smc + SM_WHI);
        uint32_t* wl = (uint32_t*)(smc + SM_WLO);
        for (int i = tid; i < WQ_U32; i += 256) { wh[i] = d_whi[i]; wl[i] = d_wlo[i]; }
    }
    __syncthreads();                           // ssel ready

    const int w  = tid >> 5, l = tid & 31;
    const int lq = l >> 2, lr = l & 3;
    const size_t xb_base = ((size_t)(b * C_)) << 16;

    #pragma unroll 1
    for (int ti = 0; ti < 8; ti++) {
        const int r0 = rgbase + ti;

        // ---- stage into 3-slot ring: rows r0-1..r0+1 first tile, r0+1 after
        const int nrows = (ti == 0) ? 3 : 1;
        const int gbase = (ti == 0) ? (r0 - 1) : (r0 + 1);
        for (int idx = tid; idx < nrows * 2080; idx += 256) {
            int j   = idx / 2080;
            int r2  = idx % 2080;
            int p   = r2 / 130;
            int col = r2 % 130;
            int g   = gbase + j;
            int sl  = (g + 3) % 3;
            float v = 0.0f;
            int gc = c0 + col - 1;
            if ((unsigned)g < 256u && (unsigned)gc < 256u)
                v = x[xb_base + ((size_t)ssel[p] << 16) + (g << 8) + gc];
            __nv_bfloat16 hv = __float2bfloat16_rn(v);
            __nv_bfloat16 lv = __float2bfloat16_rn(v - __bfloat162float(hv));
            int p2 = p >> 1;
            int s2 = (((p2 & 3) * 2 + (p2 >> 2)) << 1) + (p & 1);
            int hidx = (sl * 132 + col) * HPC + s2;
            xs_hi[hidx] = hv;
            xs_lo[hidx] = lv;
        }
        __syncthreads();                       // ring ready

        int rbu[3];
        #pragma unroll
        for (int kh = 0; kh < 3; kh++)
            rbu[kh] = ((r0 - 1 + kh + 3) % 3) * SLOT_U32;

        float acc[8][4];
        #pragma unroll
        for (int ni = 0; ni < 8; ni++)
            #pragma unroll
            for (int r = 0; r < 4; r++) acc[ni][r] = 0.0f;

        #pragma unroll
        for (int chunk = 0; chunk < 9; chunk++) {
            const int kh = chunk / 3, kw = chunk % 3;
            uint4 BH[4];
            #pragma unroll
            for (int qq = 0; qq < 4; qq++)
                BH[qq] = ws_hi4[(chunk * 4 + qq) * 32 + l];

            const int au = rbu[kh] + (w * 16 + lq + kw) * UPC + lr * 2;
            uint2 t0 = *(const uint2*)(xh_u + au);
            uint2 t1 = *(const uint2*)(xh_u + au + 8 * UPC);
            uint32_t A[4] = { t0.x, t1.x, t0.y, t1.y };
            uint2 s0 = *(const uint2*)(xl_u + au);
            uint2 s1 = *(const uint2*)(xl_u + au + 8 * UPC);
            uint32_t AL[4] = { s0.x, s1.x, s0.y, s1.y };

            #pragma unroll
            for (int qq = 0; qq < 4; qq++) {
                mma_bf16b(acc[2 * qq],     A, BH[qq].x, BH[qq].y);
                mma_bf16b(acc[2 * qq + 1], A, BH[qq].z, BH[qq].w);
            }
            #pragma unroll
            for (int qq = 0; qq < 4; qq++) {
                mma_bf16b(acc[2 * qq],     AL, BH[qq].x, BH[qq].y);
                mma_bf16b(acc[2 * qq + 1], AL, BH[qq].z, BH[qq].w);
            }
            #pragma unroll
            for (int qq = 0; qq < 4; qq++) {
                uint4 BL = ws_lo4[(chunk * 4 + qq) * 32 + l];
                mma_bf16b(acc[2 * qq],     A, BL.x, BL.y);
                mma_bf16b(acc[2 * qq + 1], A, BL.z, BL.w);
            }
        }

        // ---- epilogue ----
        const int pix = w * 16 + lq;
        float* obase = out + (((size_t)(b * OUTC_)) << 16) + (r0 << 8) + c0 + pix;
        #pragma unroll
        for (int ni = 0; ni < 8; ni++) {
            const int oc0 = ni * 8 + lr * 2;
            float* p0 = obase + ((size_t)oc0 << 16);
            float* p1 = p0 + HW_;
            p0[0] = acc[ni][0] + sbias[oc0];
            p1[0] = acc[ni][1] + sbias[oc0 + 1];
            p0[8] = acc[ni][2] + sbias[oc0];
            p1[8] = acc[ni][3] + sbias[oc0 + 1];
        }
        __syncthreads();                       // protect ring before next stage
    }
}

// ---------------- launch ----------------------------------------------------
extern "C" void kernel_launch(void* const* d_in, const int* in_sizes, int n_in,
                              void* d_out, int out_size) {
    (void)in_sizes; (void)n_in; (void)out_size;
    const float* x    = (const float*)d_in[0];
    const float* wgt  = (const float*)d_in[1];
    const float* bias = (const float*)d_in[2];
    float* out = (float*)d_out;

    cudaFuncSetAttribute(conv_copy_kernel,
                         cudaFuncAttributeMaxDynamicSharedMemorySize, SM_TOTAL);
    cudaFuncSetAttribute(conv_copy_kernel,
                         cudaFuncAttributePreferredSharedMemoryCarveout, 100);

    prep_W_kernel<<<1, 256>>>(wgt);
    channel_stats_kernel<<<B_ * C_, 1024>>>(x);
    topk_kernel<<<1, 8>>>();
    conv_copy_kernel<<<GRID_, 256, SM_TOTAL>>>(x, bias, out);
}